// round 1
// baseline (speedup 1.0000x reference)
#include <cuda_runtime.h>
#include <math.h>

#define CDIM 128
#define HNUM 4
#define DDIM 32
#define LNUM 2
#define MAXN 40000
#define MAXE 250000
#define INV_SQRT_D 0.17677669529663687f

// ---------------- static scratch (no allocs allowed) ----------------
__device__ float g_xa[MAXN * CDIM];
__device__ float g_xb[MAXN * CDIM];
__device__ float g_ka[MAXN * CDIM];
__device__ float g_va[MAXN * CDIM];
__device__ float g_qa[MAXN * CDIM];
__device__ float g_kb[MAXN * CDIM];
__device__ float g_vb[MAXN * CDIM];
__device__ float g_qb[MAXN * CDIM];
__device__ float g_agga[MAXN * CDIM];
__device__ float g_aggb[MAXN * CDIM];
__device__ float g_wfold[2][2][2][CDIM * CDIM]; // [l][type][k-or-v][128*128]
__device__ float g_bfold[2][2][2][CDIM];
__device__ int g_rp_ab[MAXN + 1];
__device__ int g_rp_ba[MAXN + 1];
__device__ int g_cnt[MAXN];
__device__ int g_cur[MAXN];
__device__ int g_src_ab[MAXE];
__device__ int g_src_ba[MAXE];

// ---------------- fold a_rel/m_rel (block-diag per head) into k_w/v_w ----------------
// k'[n,h,e] = sum_d k[n,h,d]*rel[h,d,e]  =>  W'[i, h*32+e] = sum_d W[i, h*32+d]*rel[h,d,e]
__global__ void fold_kernel(const float* __restrict__ kw, const float* __restrict__ kb,
                            const float* __restrict__ vw, const float* __restrict__ vb,
                            const float* __restrict__ arel, const float* __restrict__ mrel) {
    int tid = blockIdx.x * blockDim.x + threadIdx.x;
    if (tid < 131072) {
        int col = tid & 127;
        int i = (tid >> 7) & 127;
        int kv = (tid >> 14) & 1;
        int t = (tid >> 15) & 1;
        int l = (tid >> 16) & 1;
        int h = col >> 5;
        int e = col & 31;
        const float* W = kv ? vw : kw;
        const float* R = kv ? mrel : arel;
        const float* wblk = W + (l * 2 + t) * CDIM * CDIM;
        const float* rblk = R + ((l * 2 + t) * HNUM + h) * DDIM * DDIM;
        float s = 0.f;
#pragma unroll
        for (int d = 0; d < 32; d++)
            s += wblk[i * CDIM + h * 32 + d] * rblk[d * 32 + e];
        g_wfold[l][t][kv][i * CDIM + col] = s;
    } else if (tid < 131072 + 1024) {
        int idx = tid - 131072;
        int col = idx & 127;
        int kv = (idx >> 7) & 1;
        int t = (idx >> 8) & 1;
        int l = (idx >> 9) & 1;
        int h = col >> 5;
        int e = col & 31;
        const float* B = kv ? vb : kb;
        const float* R = kv ? mrel : arel;
        const float* bblk = B + (l * 2 + t) * CDIM;
        const float* rblk = R + ((l * 2 + t) * HNUM + h) * DDIM * DDIM;
        float s = 0.f;
#pragma unroll
        for (int d = 0; d < 32; d++)
            s += bblk[h * 32 + d] * rblk[d * 32 + e];
        g_bfold[l][t][kv][col] = s;
    }
}

// ---------------- generic GEMM: out[M,128] = f(A[M,K] @ W[K,128] + b) ----------------
// mode 0: plain   mode 1: relu   mode 2: gelu(A) on load + skip-mix epilogue
__global__ void __launch_bounds__(256) gemm_kernel(
    const float* __restrict__ A, const float* __restrict__ W,
    const float* __restrict__ bias, float* __restrict__ Out,
    int M, int K, int mode,
    const float* __restrict__ xold, const float* __restrict__ skipPtr, int skipIdx) {
    __shared__ float As[32][129];   // [k][m], padded
    __shared__ float Ws[32][CDIM];  // [k][n]
    int tid = threadIdx.x;
    int tcol = tid & 15;   // 16 col-groups * 8 cols
    int trow = tid >> 4;   // 16 row-groups * 8 rows
    int m0 = blockIdx.x * 128;

    float acc[8][8];
#pragma unroll
    for (int r = 0; r < 8; r++)
#pragma unroll
        for (int c = 0; c < 8; c++) acc[r][c] = 0.f;

    for (int k0 = 0; k0 < K; k0 += 32) {
#pragma unroll
        for (int i = 0; i < 16; i++) {
            int idx = tid + i * 256;
            int r = idx >> 5, kk = idx & 31;
            int row = m0 + r;
            float v = (row < M) ? A[row * K + k0 + kk] : 0.f;
            if (mode == 2) v = 0.5f * v * (1.f + erff(v * 0.70710678118654752f));
            As[kk][r] = v;
        }
#pragma unroll
        for (int i = 0; i < 16; i++) {
            int idx = tid + i * 256;
            int kr = idx >> 7, col = idx & 127;
            Ws[kr][col] = W[(k0 + kr) * CDIM + col];
        }
        __syncthreads();
#pragma unroll 4
        for (int kk = 0; kk < 32; kk++) {
            float b[8];
            *(float4*)&b[0] = *(const float4*)&Ws[kk][tcol * 8];
            *(float4*)&b[4] = *(const float4*)&Ws[kk][tcol * 8 + 4];
            float a[8];
#pragma unroll
            for (int r = 0; r < 8; r++) a[r] = As[kk][trow * 8 + r];
#pragma unroll
            for (int r = 0; r < 8; r++)
#pragma unroll
                for (int c = 0; c < 8; c++) acc[r][c] += a[r] * b[c];
        }
        __syncthreads();
    }

    float sg = 1.f, omsg = 0.f;
    if (mode == 2) {
        float sk = skipPtr[skipIdx];
        sg = 1.f / (1.f + expf(-sk));
        omsg = 1.f - sg;
    }
    float bv[8];
    *(float4*)&bv[0] = *(const float4*)&bias[tcol * 8];
    *(float4*)&bv[4] = *(const float4*)&bias[tcol * 8 + 4];
#pragma unroll
    for (int r = 0; r < 8; r++) {
        int row = m0 + trow * 8 + r;
        if (row >= M) continue;
        float o[8];
#pragma unroll
        for (int c = 0; c < 8; c++) {
            float v = acc[r][c] + bv[c];
            if (mode == 1) v = fmaxf(v, 0.f);
            else if (mode == 2) v = sg * v + omsg * xold[row * CDIM + tcol * 8 + c];
            o[c] = v;
        }
        *(float4*)&Out[row * CDIM + tcol * 8] = *(float4*)&o[0];
        *(float4*)&Out[row * CDIM + tcol * 8 + 4] = *(float4*)&o[4];
    }
}

// ---------------- CSR build helpers ----------------
__global__ void zero_int(int* p, int n) {
    int i = blockIdx.x * blockDim.x + threadIdx.x;
    if (i < n) p[i] = 0;
}
__global__ void hist_kernel(const int* __restrict__ dst, int n, int* __restrict__ cnt) {
    int i = blockIdx.x * blockDim.x + threadIdx.x;
    if (i < n) atomicAdd(&cnt[dst[i]], 1);
}
__global__ void scan_exclusive(const int* __restrict__ cnt, int* __restrict__ rowptr, int n) {
    __shared__ int buf[1024];
    __shared__ int carry;
    if (threadIdx.x == 0) carry = 0;
    __syncthreads();
    for (int base = 0; base < n; base += 1024) {
        int i = base + threadIdx.x;
        int v = (i < n) ? cnt[i] : 0;
        buf[threadIdx.x] = v;
        __syncthreads();
        for (int off = 1; off < 1024; off <<= 1) {
            int t = (threadIdx.x >= off) ? buf[threadIdx.x - off] : 0;
            __syncthreads();
            buf[threadIdx.x] += t;
            __syncthreads();
        }
        if (i < n) rowptr[i] = carry + buf[threadIdx.x] - v;
        __syncthreads();
        if (threadIdx.x == 0) carry += buf[1023];
        __syncthreads();
    }
    if (threadIdx.x == 0) rowptr[n] = carry;
}
__global__ void copy_int(const int* __restrict__ a, int* __restrict__ b, int n) {
    int i = blockIdx.x * blockDim.x + threadIdx.x;
    if (i < n) b[i] = a[i];
}
__global__ void scatter_kernel(const int* __restrict__ src, const int* __restrict__ dst, int n,
                               int* __restrict__ cur, int* __restrict__ out) {
    int i = blockIdx.x * blockDim.x + threadIdx.x;
    if (i < n) {
        int pos = atomicAdd(&cur[dst[i]], 1);
        out[pos] = src[i];
    }
}

// ---------------- per-destination online-softmax aggregation ----------------
// one warp per destination node; lane owns 4 channels (head = lane>>3)
__global__ void __launch_bounds__(256) agg_kernel(
    const float* __restrict__ Kf, const float* __restrict__ Vf,
    const float* __restrict__ Qf, const int* __restrict__ rowptr,
    const int* __restrict__ srcidx, const float* __restrict__ prel,
    float* __restrict__ Out, int Ndst) {
    int w = (blockIdx.x * blockDim.x + threadIdx.x) >> 5;
    int lane = threadIdx.x & 31;
    if (w >= Ndst) return;
    const float4 q = *(const float4*)&Qf[w * CDIM + lane * 4];
    float pr = prel[lane >> 3] * INV_SQRT_D;
    float m = -INFINITY, s = 0.f;
    float ax = 0.f, ay = 0.f, az = 0.f, aw2 = 0.f;
    int e0 = rowptr[w], e1 = rowptr[w + 1];
    for (int j = e0; j < e1; j++) {
        int src = srcidx[j];
        const float4 k = *(const float4*)&Kf[src * CDIM + lane * 4];
        const float4 v = *(const float4*)&Vf[src * CDIM + lane * 4];
        float d = q.x * k.x + q.y * k.y + q.z * k.z + q.w * k.w;
        d += __shfl_xor_sync(0xffffffffu, d, 1);
        d += __shfl_xor_sync(0xffffffffu, d, 2);
        d += __shfl_xor_sync(0xffffffffu, d, 4);
        float logit = d * pr;
        float mn = fmaxf(m, logit);
        float sc = expf(m - mn);     // first iter: exp(-inf)=0
        float wg = expf(logit - mn);
        s = s * sc + wg;
        ax = ax * sc + wg * v.x;
        ay = ay * sc + wg * v.y;
        az = az * sc + wg * v.z;
        aw2 = aw2 * sc + wg * v.w;
        m = mn;
    }
    float inv = 1.f / (s + 1e-16f);
    float4 o = make_float4(ax * inv, ay * inv, az * inv, aw2 * inv);
    *(float4*)&Out[w * CDIM + lane * 4] = o;
}

__global__ void copy_out_kernel(const float* __restrict__ a, float* __restrict__ o, int n) {
    int i = blockIdx.x * blockDim.x + threadIdx.x;
    if (i * 4 < n) {
        *(float4*)&o[i * 4] = *(const float4*)&a[i * 4];
    }
}

// ---------------- driver ----------------
extern "C" void kernel_launch(void* const* d_in, const int* in_sizes, int n_in,
                              void* d_out, int out_size) {
    const float* x_a = (const float*)d_in[0];
    const float* x_b = (const float*)d_in[1];
    const int* edge_ab = (const int*)d_in[2];
    const int* edge_ba = (const int*)d_in[3];
    const float* lin_a_w = (const float*)d_in[4];
    const float* lin_a_b = (const float*)d_in[5];
    const float* lin_b_w = (const float*)d_in[6];
    const float* lin_b_b = (const float*)d_in[7];
    const float* k_w = (const float*)d_in[8];
    const float* q_w = (const float*)d_in[10];
    const float* q_b = (const float*)d_in[11];
    const float* v_w = (const float*)d_in[12];
    const float* k_b = (const float*)d_in[9];
    const float* v_b = (const float*)d_in[13];
    const float* a_rel = (const float*)d_in[14];
    const float* m_rel = (const float*)d_in[15];
    const float* p_rel = (const float*)d_in[16];
    const float* a_lin_w = (const float*)d_in[17];
    const float* a_lin_b = (const float*)d_in[18];
    const float* skip = (const float*)d_in[19];
    float* out = (float*)d_out;

    int DA = in_sizes[4] / CDIM;
    int DB = in_sizes[6] / CDIM;
    int NA = in_sizes[0] / DA;
    int NB = in_sizes[1] / DB;
    int Eab = in_sizes[2] / 2;
    int Eba = in_sizes[3] / 2;

    float *xa, *xb, *ka, *va, *qa, *kb, *vb, *qb, *agga, *aggb, *wfold, *bfold;
    int *rp_ab, *rp_ba, *cnt, *cur, *src_ab, *src_ba;
    cudaGetSymbolAddress((void**)&xa, g_xa);
    cudaGetSymbolAddress((void**)&xb, g_xb);
    cudaGetSymbolAddress((void**)&ka, g_ka);
    cudaGetSymbolAddress((void**)&va, g_va);
    cudaGetSymbolAddress((void**)&qa, g_qa);
    cudaGetSymbolAddress((void**)&kb, g_kb);
    cudaGetSymbolAddress((void**)&vb, g_vb);
    cudaGetSymbolAddress((void**)&qb, g_qb);
    cudaGetSymbolAddress((void**)&agga, g_agga);
    cudaGetSymbolAddress((void**)&aggb, g_aggb);
    cudaGetSymbolAddress((void**)&wfold, g_wfold);
    cudaGetSymbolAddress((void**)&bfold, g_bfold);
    cudaGetSymbolAddress((void**)&rp_ab, g_rp_ab);
    cudaGetSymbolAddress((void**)&rp_ba, g_rp_ba);
    cudaGetSymbolAddress((void**)&cnt, g_cnt);
    cudaGetSymbolAddress((void**)&cur, g_cur);
    cudaGetSymbolAddress((void**)&src_ab, g_src_ab);
    cudaGetSymbolAddress((void**)&src_ba, g_src_ba);

    // 1. fold rel matrices into K/V weights
    fold_kernel<<<(131072 + 1024 + 255) / 256, 256>>>(k_w, k_b, v_w, v_b, a_rel, m_rel);

    // 2. input linears (+relu)
    gemm_kernel<<<(NA + 127) / 128, 256>>>(x_a, lin_a_w, lin_a_b, xa, NA, DA, 1, nullptr, nullptr, 0);
    gemm_kernel<<<(NB + 127) / 128, 256>>>(x_b, lin_b_w, lin_b_b, xb, NB, DB, 1, nullptr, nullptr, 0);

    // 3. build CSRs (by destination) — topology is layer-invariant
    {
        zero_int<<<(NB + 255) / 256, 256>>>(cnt, NB);
        hist_kernel<<<(Eab + 255) / 256, 256>>>(edge_ab + Eab, Eab, cnt);
        scan_exclusive<<<1, 1024>>>(cnt, rp_ab, NB);
        copy_int<<<(NB + 255) / 256, 256>>>(rp_ab, cur, NB);
        scatter_kernel<<<(Eab + 255) / 256, 256>>>(edge_ab, edge_ab + Eab, Eab, cur, src_ab);

        zero_int<<<(NA + 255) / 256, 256>>>(cnt, NA);
        hist_kernel<<<(Eba + 255) / 256, 256>>>(edge_ba + Eba, Eba, cnt);
        scan_exclusive<<<1, 1024>>>(cnt, rp_ba, NA);
        copy_int<<<(NA + 255) / 256, 256>>>(rp_ba, cur, NA);
        scatter_kernel<<<(Eba + 255) / 256, 256>>>(edge_ba, edge_ba + Eba, Eba, cur, src_ba);
    }

    const int CC = CDIM * CDIM;
    for (int l = 0; l < LNUM; l++) {
        const float* wf = wfold;
        const float* bf = bfold;
        // offsets into fold arrays: ((l*2+t)*2+kv)
        const float* wKA = wf + ((l * 2 + 0) * 2 + 0) * CC;
        const float* wVA = wf + ((l * 2 + 0) * 2 + 1) * CC;
        const float* wKB = wf + ((l * 2 + 1) * 2 + 0) * CC;
        const float* wVB = wf + ((l * 2 + 1) * 2 + 1) * CC;
        const float* bKA = bf + ((l * 2 + 0) * 2 + 0) * CDIM;
        const float* bVA = bf + ((l * 2 + 0) * 2 + 1) * CDIM;
        const float* bKB = bf + ((l * 2 + 1) * 2 + 0) * CDIM;
        const float* bVB = bf + ((l * 2 + 1) * 2 + 1) * CDIM;

        int gA = (NA + 127) / 128, gB = (NB + 127) / 128;
        gemm_kernel<<<gA, 256>>>(xa, wKA, bKA, ka, NA, CDIM, 0, nullptr, nullptr, 0);
        gemm_kernel<<<gA, 256>>>(xa, wVA, bVA, va, NA, CDIM, 0, nullptr, nullptr, 0);
        gemm_kernel<<<gA, 256>>>(xa, q_w + (l * 2 + 0) * CC, q_b + (l * 2 + 0) * CDIM, qa, NA, CDIM, 0, nullptr, nullptr, 0);
        gemm_kernel<<<gB, 256>>>(xb, wKB, bKB, kb, NB, CDIM, 0, nullptr, nullptr, 0);
        gemm_kernel<<<gB, 256>>>(xb, wVB, bVB, vb, NB, CDIM, 0, nullptr, nullptr, 0);
        gemm_kernel<<<gB, 256>>>(xb, q_w + (l * 2 + 1) * CC, q_b + (l * 2 + 1) * CDIM, qb, NB, CDIM, 0, nullptr, nullptr, 0);

        // A -> B (relation 0): out_b ; B -> A (relation 1): out_a
        agg_kernel<<<(NB * 32 + 255) / 256, 256>>>(ka, va, qb, rp_ab, src_ab,
                                                   p_rel + (l * 2 + 0) * HNUM, aggb, NB);
        agg_kernel<<<(NA * 32 + 255) / 256, 256>>>(kb, vb, qa, rp_ba, src_ba,
                                                   p_rel + (l * 2 + 1) * HNUM, agga, NA);

        // gelu + a_lin + skip-mix (in place on xa/xb)
        gemm_kernel<<<gA, 256>>>(agga, a_lin_w + (l * 2 + 0) * CC, a_lin_b + (l * 2 + 0) * CDIM,
                                 xa, NA, CDIM, 2, xa, skip, l * 2 + 0);
        gemm_kernel<<<gB, 256>>>(aggb, a_lin_w + (l * 2 + 1) * CC, a_lin_b + (l * 2 + 1) * CDIM,
                                 xb, NB, CDIM, 2, xb, skip, l * 2 + 1);
    }

    // 4. concatenate (xa, xb) into output
    copy_out_kernel<<<(NA * CDIM / 4 + 255) / 256, 256>>>(xa, out, NA * CDIM);
    copy_out_kernel<<<(NB * CDIM / 4 + 255) / 256, 256>>>(xb, out + NA * CDIM, NB * CDIM);
}

// round 3
// speedup vs baseline: 1.4480x; 1.4480x over previous
#include <cuda_runtime.h>
#include <cuda_bf16.h>
#include <math.h>
#include <stdint.h>

#define CDIM 128
#define HNUM 4
#define DDIM 32
#define LNUM 2
#define MAXN 40000
#define MAXE 250000
#define INV_SQRT_D 0.17677669529663687f

// ---------------- static scratch (no allocs allowed) ----------------
__device__ float g_xa[MAXN * CDIM];
__device__ float g_xb[MAXN * CDIM];
__device__ float g_ka[MAXN * CDIM];
__device__ float g_va[MAXN * CDIM];
__device__ float g_qa[MAXN * CDIM];
__device__ float g_kb[MAXN * CDIM];
__device__ float g_vb[MAXN * CDIM];
__device__ float g_qb[MAXN * CDIM];
__device__ float g_agga[MAXN * CDIM];
__device__ float g_aggb[MAXN * CDIM];
__device__ float g_wfold[2][2][2][CDIM * CDIM]; // [l][t][k-or-v]
__device__ float g_bfold[2][2][2][CDIM];
// weight slots: [slot][hi/lo] each 32KB: [n=128][k-pitch=128] bf16, XOR-swizzled
__device__ __align__(16) unsigned char g_wt[18 * 2 * 32768];
__device__ int g_rp_ab[MAXN + 1];
__device__ int g_rp_ba[MAXN + 1];
__device__ int g_cnt[MAXN];
__device__ int g_cur[MAXN];
__device__ int g_src_ab[MAXE];
__device__ int g_src_ba[MAXE];

// swizzled byte offset for element (row, k) in a [row][k] bf16 tile, pitch 128 elems
__device__ __forceinline__ uint32_t tile_off(int row, int k) {
    return (uint32_t)(row * 256 + (((k >> 3) ^ (row & 7)) << 4) + ((k & 7) << 1));
}

__device__ __forceinline__ uint32_t smem_u32(const void* p) {
    uint32_t a;
    asm("{ .reg .u64 t; cvta.to.shared.u64 t, %1; cvt.u32.u64 %0, t; }" : "=r"(a) : "l"(p));
    return a;
}
__device__ __forceinline__ void ldsm4(uint32_t& r0, uint32_t& r1, uint32_t& r2, uint32_t& r3, uint32_t addr) {
    asm volatile("ldmatrix.sync.aligned.m8n8.x4.shared.b16 {%0,%1,%2,%3}, [%4];"
                 : "=r"(r0), "=r"(r1), "=r"(r2), "=r"(r3) : "r"(addr));
}
__device__ __forceinline__ void mma16816(float* c, const uint32_t* a, const uint32_t* b) {
    asm volatile(
        "mma.sync.aligned.m16n8k16.row.col.f32.bf16.bf16.f32 "
        "{%0,%1,%2,%3}, {%4,%5,%6,%7}, {%8,%9}, {%0,%1,%2,%3};"
        : "+f"(c[0]), "+f"(c[1]), "+f"(c[2]), "+f"(c[3])
        : "r"(a[0]), "r"(a[1]), "r"(a[2]), "r"(a[3]), "r"(b[0]), "r"(b[1]));
}

// ---------------- fold a_rel/m_rel (block-diag per head) into k_w/v_w ----------------
__global__ void fold_kernel(const float* __restrict__ kw, const float* __restrict__ kb,
                            const float* __restrict__ vw, const float* __restrict__ vb,
                            const float* __restrict__ arel, const float* __restrict__ mrel) {
    int tid = blockIdx.x * blockDim.x + threadIdx.x;
    if (tid < 131072) {
        int col = tid & 127;
        int i = (tid >> 7) & 127;
        int kv = (tid >> 14) & 1;
        int t = (tid >> 15) & 1;
        int l = (tid >> 16) & 1;
        int h = col >> 5;
        int e = col & 31;
        const float* W = kv ? vw : kw;
        const float* R = kv ? mrel : arel;
        const float* wblk = W + (l * 2 + t) * CDIM * CDIM;
        const float* rblk = R + ((l * 2 + t) * HNUM + h) * DDIM * DDIM;
        float s = 0.f;
#pragma unroll
        for (int d = 0; d < 32; d++)
            s += wblk[i * CDIM + h * 32 + d] * rblk[d * 32 + e];
        g_wfold[l][t][kv][i * CDIM + col] = s;
    } else if (tid < 131072 + 1024) {
        int idx = tid - 131072;
        int col = idx & 127;
        int kv = (idx >> 7) & 1;
        int t = (idx >> 8) & 1;
        int l = (idx >> 9) & 1;
        int h = col >> 5;
        int e = col & 31;
        const float* B = kv ? vb : kb;
        const float* R = kv ? mrel : arel;
        const float* bblk = B + (l * 2 + t) * CDIM;
        const float* rblk = R + ((l * 2 + t) * HNUM + h) * DDIM * DDIM;
        float s = 0.f;
#pragma unroll
        for (int d = 0; d < 32; d++)
            s += bblk[h * 32 + d] * rblk[d * 32 + e];
        g_bfold[l][t][kv][col] = s;
    }
}

// ---------------- convert weights: transpose to [n][k], split hi/lo, swizzle ----------------
// slot 0: lin_a_w (K=64); slot 1: lin_b_w (K=32); slot 2+(lt*4+j): j=0 Kfold, 1 Vfold, 2 q_w, 3 a_lin_w
__global__ void convert_weights(const float* __restrict__ lin_a_w, const float* __restrict__ lin_b_w,
                                const float* __restrict__ q_w, const float* __restrict__ a_lin_w) {
    int tid = blockIdx.x * blockDim.x + threadIdx.x;
    if (tid >= 18 * 16384) return;
    int s = tid >> 14;
    int rem = tid & 16383;
    int n = rem >> 7;
    int k = rem & 127;
    float val = 0.f;
    const float* wfold = &g_wfold[0][0][0][0];
    if (s == 0) {
        if (k < 64) val = lin_a_w[k * CDIM + n];
    } else if (s == 1) {
        if (k < 32) val = lin_b_w[k * CDIM + n];
    } else {
        int q = s - 2;
        int j = q & 3;
        int lt = q >> 2;
        if (j == 0) val = wfold[(lt * 2 + 0) * 16384 + k * CDIM + n];
        else if (j == 1) val = wfold[(lt * 2 + 1) * 16384 + k * CDIM + n];
        else if (j == 2) val = q_w[lt * 16384 + k * CDIM + n];
        else val = a_lin_w[lt * 16384 + k * CDIM + n];
    }
    __nv_bfloat16 hi = __float2bfloat16(val);
    __nv_bfloat16 lo = __float2bfloat16(val - __bfloat162float(hi));
    uint32_t off = tile_off(n, k);
    *(__nv_bfloat16*)(g_wt + (size_t)(s * 2 + 0) * 32768 + off) = hi;
    *(__nv_bfloat16*)(g_wt + (size_t)(s * 2 + 1) * 32768 + off) = lo;
}

// ---------------- tensor-core GEMM via mma.sync: Out[M,128] = act(A[M,K] @ W + b) ----------------
struct GemmArgs {
    const float* A;
    const unsigned char* Wslot[3]; // hi at +0, lo at +32768
    const float* bias[3];
    float* outp[3];
    const float* xold;
    const float* skipPtr;
    int M, K, nOut, mode, skipIdx;
};

#define SM_AHI 0
#define SM_ALO 32768
#define SM_WHI 65536
#define SM_WLO 98304
#define SMEM_BYTES 131072

__global__ void __launch_bounds__(256, 1) mm_gemm(GemmArgs g) {
    extern __shared__ __align__(16) unsigned char smem[];
    uint32_t sb = smem_u32(smem);
    int tid = threadIdx.x;
    int wid = tid >> 5, lane = tid & 31;
    int warp_m = wid & 3, warp_n = wid >> 2;
    int m0 = blockIdx.x * 128;

    // zero A region if K-padded or partial M tile
    if (g.K != 128 || m0 + 128 > g.M) {
        uint4 z = make_uint4(0, 0, 0, 0);
        for (int i = tid; i < 65536 / 16; i += 256) ((uint4*)(smem + SM_AHI))[i] = z;
        __syncthreads();
    }

    // load + convert A (optional gelu) into split bf16 swizzled tiles
    {
        int kvec = g.K >> 2;
        int tot = 128 * kvec;
        for (int i = tid; i < tot; i += 256) {
            int row = i / kvec, c4 = i - row * kvec;
            int grow = m0 + row;
            if (grow < g.M) {
                float4 v = *(const float4*)(g.A + (size_t)grow * g.K + c4 * 4);
                if (g.mode == 2) {
                    v.x = 0.5f * v.x * (1.f + erff(v.x * 0.70710678118654752f));
                    v.y = 0.5f * v.y * (1.f + erff(v.y * 0.70710678118654752f));
                    v.z = 0.5f * v.z * (1.f + erff(v.z * 0.70710678118654752f));
                    v.w = 0.5f * v.w * (1.f + erff(v.w * 0.70710678118654752f));
                }
                __nv_bfloat16 hx = __float2bfloat16(v.x), hy = __float2bfloat16(v.y);
                __nv_bfloat16 hz = __float2bfloat16(v.z), hw = __float2bfloat16(v.w);
                __nv_bfloat162 h01, h23, l01, l23;
                h01.x = hx; h01.y = hy; h23.x = hz; h23.y = hw;
                l01.x = __float2bfloat16(v.x - __bfloat162float(hx));
                l01.y = __float2bfloat16(v.y - __bfloat162float(hy));
                l23.x = __float2bfloat16(v.z - __bfloat162float(hz));
                l23.y = __float2bfloat16(v.w - __bfloat162float(hw));
                uint32_t off = tile_off(row, c4 * 4);
                uint2 hv, lv;
                hv.x = *(uint32_t*)&h01; hv.y = *(uint32_t*)&h23;
                lv.x = *(uint32_t*)&l01; lv.y = *(uint32_t*)&l23;
                *(uint2*)(smem + SM_AHI + off) = hv;
                *(uint2*)(smem + SM_ALO + off) = lv;
            }
        }
    }

    for (int o = 0; o < g.nOut; o++) {
        __syncthreads();
        // stage W hi+lo (64KB contiguous, already swizzled)
        {
            const uint4* src = (const uint4*)g.Wslot[o];
            for (int i = tid; i < 65536 / 16; i += 256)
                ((uint4*)(smem + SM_WHI))[i] = src[i];
        }
        __syncthreads();

        float acc[2][8][4];
#pragma unroll
        for (int mt = 0; mt < 2; mt++)
#pragma unroll
            for (int nt = 0; nt < 8; nt++)
#pragma unroll
                for (int e = 0; e < 4; e++) acc[mt][nt][e] = 0.f;

        for (int kc = 0; kc < g.K; kc += 16) {
            int kch = kc >> 3;
            uint32_t ah[8], al[8], bh[16], bl[16];
#pragma unroll
            for (int mt = 0; mt < 2; mt++) {
                int r = warp_m * 32 + mt * 16 + (lane & 15);
                uint32_t addr = sb + SM_AHI + r * 256 + ((((kch + (lane >> 4)) ^ (r & 7))) << 4);
                ldsm4(ah[mt * 4 + 0], ah[mt * 4 + 1], ah[mt * 4 + 2], ah[mt * 4 + 3], addr);
                ldsm4(al[mt * 4 + 0], al[mt * 4 + 1], al[mt * 4 + 2], al[mt * 4 + 3], addr + 32768);
            }
#pragma unroll
            for (int p = 0; p < 4; p++) {
                int n = warp_n * 64 + p * 16 + ((lane >> 4) << 3) + (lane & 7);
                uint32_t addr = sb + SM_WHI + n * 256 + ((((kch + ((lane >> 3) & 1)) ^ (n & 7))) << 4);
                ldsm4(bh[p * 4 + 0], bh[p * 4 + 1], bh[p * 4 + 2], bh[p * 4 + 3], addr);
                ldsm4(bl[p * 4 + 0], bl[p * 4 + 1], bl[p * 4 + 2], bl[p * 4 + 3], addr + 32768);
            }
#pragma unroll
            for (int mt = 0; mt < 2; mt++)
#pragma unroll
                for (int nt = 0; nt < 8; nt++) {
                    float* c = acc[mt][nt];
                    mma16816(c, &ah[mt * 4], &bh[nt * 2]);
                    mma16816(c, &ah[mt * 4], &bl[nt * 2]);
                    mma16816(c, &al[mt * 4], &bh[nt * 2]);
                }
        }

        // epilogue straight from registers
        float sg = 1.f, om = 0.f;
        if (g.mode == 2) {
            float sk = g.skipPtr[g.skipIdx];
            sg = 1.f / (1.f + expf(-sk));
            om = 1.f - sg;
        }
        const float* bp = g.bias[o];
        float* op = g.outp[o];
        int qrow = lane >> 2, qcol = (lane & 3) * 2;
        float2 bv[8];
#pragma unroll
        for (int nt = 0; nt < 8; nt++)
            bv[nt] = *(const float2*)&bp[warp_n * 64 + nt * 8 + qcol];
#pragma unroll
        for (int mt = 0; mt < 2; mt++) {
#pragma unroll
            for (int half = 0; half < 2; half++) {
                int row = m0 + warp_m * 32 + mt * 16 + qrow + half * 8;
                if (row >= g.M) continue;
#pragma unroll
                for (int nt = 0; nt < 8; nt++) {
                    int col = warp_n * 64 + nt * 8 + qcol;
                    float vx = acc[mt][nt][half * 2 + 0] + bv[nt].x;
                    float vy = acc[mt][nt][half * 2 + 1] + bv[nt].y;
                    if (g.mode == 1) {
                        vx = fmaxf(vx, 0.f);
                        vy = fmaxf(vy, 0.f);
                    } else if (g.mode == 2) {
                        float2 xo = *(const float2*)&g.xold[(size_t)row * CDIM + col];
                        vx = sg * vx + om * xo.x;
                        vy = sg * vy + om * xo.y;
                    }
                    float2 ov; ov.x = vx; ov.y = vy;
                    *(float2*)&op[(size_t)row * CDIM + col] = ov;
                }
            }
        }
    }
}

// ---------------- CSR build helpers ----------------
__global__ void zero_int(int* p, int n) {
    int i = blockIdx.x * blockDim.x + threadIdx.x;
    if (i < n) p[i] = 0;
}
__global__ void hist_kernel(const int* __restrict__ dst, int n, int* __restrict__ cnt) {
    int i = blockIdx.x * blockDim.x + threadIdx.x;
    if (i < n) atomicAdd(&cnt[dst[i]], 1);
}
__global__ void scan_exclusive(const int* __restrict__ cnt, int* __restrict__ rowptr, int n) {
    __shared__ int buf[1024];
    __shared__ int carry;
    if (threadIdx.x == 0) carry = 0;
    __syncthreads();
    for (int base = 0; base < n; base += 1024) {
        int i = base + threadIdx.x;
        int v = (i < n) ? cnt[i] : 0;
        buf[threadIdx.x] = v;
        __syncthreads();
        for (int off = 1; off < 1024; off <<= 1) {
            int t = (threadIdx.x >= off) ? buf[threadIdx.x - off] : 0;
            __syncthreads();
            buf[threadIdx.x] += t;
            __syncthreads();
        }
        if (i < n) rowptr[i] = carry + buf[threadIdx.x] - v;
        __syncthreads();
        if (threadIdx.x == 0) carry += buf[1023];
        __syncthreads();
    }
    if (threadIdx.x == 0) rowptr[n] = carry;
}
__global__ void copy_int(const int* __restrict__ a, int* __restrict__ b, int n) {
    int i = blockIdx.x * blockDim.x + threadIdx.x;
    if (i < n) b[i] = a[i];
}
__global__ void scatter_kernel(const int* __restrict__ src, const int* __restrict__ dst, int n,
                               int* __restrict__ cur, int* __restrict__ out) {
    int i = blockIdx.x * blockDim.x + threadIdx.x;
    if (i < n) {
        int pos = atomicAdd(&cur[dst[i]], 1);
        out[pos] = src[i];
    }
}

// ---------------- per-destination online-softmax aggregation ----------------
__global__ void __launch_bounds__(256) agg_kernel(
    const float* __restrict__ Kf, const float* __restrict__ Vf,
    const float* __restrict__ Qf, const int* __restrict__ rowptr,
    const int* __restrict__ srcidx, const float* __restrict__ prel,
    float* __restrict__ Out, int Ndst) {
    int w = (blockIdx.x * blockDim.x + threadIdx.x) >> 5;
    int lane = threadIdx.x & 31;
    if (w >= Ndst) return;
    const float4 q = *(const float4*)&Qf[w * CDIM + lane * 4];
    float pr = prel[lane >> 3] * INV_SQRT_D;
    float m = -INFINITY, s = 0.f;
    float ax = 0.f, ay = 0.f, az = 0.f, aw2 = 0.f;
    int e0 = rowptr[w], e1 = rowptr[w + 1];
    for (int j = e0; j < e1; j++) {
        int src = srcidx[j];
        const float4 k = *(const float4*)&Kf[src * CDIM + lane * 4];
        const float4 v = *(const float4*)&Vf[src * CDIM + lane * 4];
        float d = q.x * k.x + q.y * k.y + q.z * k.z + q.w * k.w;
        d += __shfl_xor_sync(0xffffffffu, d, 1);
        d += __shfl_xor_sync(0xffffffffu, d, 2);
        d += __shfl_xor_sync(0xffffffffu, d, 4);
        float logit = d * pr;
        float mn = fmaxf(m, logit);
        float sc = expf(m - mn);
        float wg = expf(logit - mn);
        s = s * sc + wg;
        ax = ax * sc + wg * v.x;
        ay = ay * sc + wg * v.y;
        az = az * sc + wg * v.z;
        aw2 = aw2 * sc + wg * v.w;
        m = mn;
    }
    float inv = 1.f / (s + 1e-16f);
    float4 o = make_float4(ax * inv, ay * inv, az * inv, aw2 * inv);
    *(float4*)&Out[w * CDIM + lane * 4] = o;
}

// ---------------- driver ----------------
static void launch_mm_gemm(const float* A, int M, int K,
                           unsigned char* wt, int s0, int s1, int s2,
                           const float* b0, const float* b1, const float* b2,
                           float* O0, float* O1, float* O2, int nOut, int mode,
                           const float* xold, const float* skipPtr, int skipIdx) {
    GemmArgs g;
    g.A = A;
    g.Wslot[0] = wt + (size_t)s0 * 65536;
    g.Wslot[1] = (s1 >= 0) ? wt + (size_t)s1 * 65536 : nullptr;
    g.Wslot[2] = (s2 >= 0) ? wt + (size_t)s2 * 65536 : nullptr;
    g.bias[0] = b0; g.bias[1] = b1; g.bias[2] = b2;
    g.outp[0] = O0; g.outp[1] = O1; g.outp[2] = O2;
    g.xold = xold; g.skipPtr = skipPtr;
    g.M = M; g.K = K; g.nOut = nOut; g.mode = mode; g.skipIdx = skipIdx;
    mm_gemm<<<(M + 127) / 128, 256, SMEM_BYTES>>>(g);
}

extern "C" void kernel_launch(void* const* d_in, const int* in_sizes, int n_in,
                              void* d_out, int out_size) {
    const float* x_a = (const float*)d_in[0];
    const float* x_b = (const float*)d_in[1];
    const int* edge_ab = (const int*)d_in[2];
    const int* edge_ba = (const int*)d_in[3];
    const float* lin_a_w = (const float*)d_in[4];
    const float* lin_a_b = (const float*)d_in[5];
    const float* lin_b_w = (const float*)d_in[6];
    const float* lin_b_b = (const float*)d_in[7];
    const float* k_w = (const float*)d_in[8];
    const float* k_b = (const float*)d_in[9];
    const float* q_w = (const float*)d_in[10];
    const float* q_b = (const float*)d_in[11];
    const float* v_w = (const float*)d_in[12];
    const float* v_b = (const float*)d_in[13];
    const float* a_rel = (const float*)d_in[14];
    const float* m_rel = (const float*)d_in[15];
    const float* p_rel = (const float*)d_in[16];
    const float* a_lin_w = (const float*)d_in[17];
    const float* a_lin_b = (const float*)d_in[18];
    const float* skip = (const float*)d_in[19];
    float* out = (float*)d_out;

    int DA = in_sizes[4] / CDIM;
    int DB = in_sizes[6] / CDIM;
    int NA = in_sizes[0] / DA;
    int NB = in_sizes[1] / DB;
    int Eab = in_sizes[2] / 2;
    int Eba = in_sizes[3] / 2;

    float *xa, *xb, *ka, *va, *qa, *kb, *vb, *qb, *agga, *aggb, *bfold;
    unsigned char* wt;
    int *rp_ab, *rp_ba, *cnt, *cur, *src_ab, *src_ba;
    cudaGetSymbolAddress((void**)&xa, g_xa);
    cudaGetSymbolAddress((void**)&xb, g_xb);
    cudaGetSymbolAddress((void**)&ka, g_ka);
    cudaGetSymbolAddress((void**)&va, g_va);
    cudaGetSymbolAddress((void**)&qa, g_qa);
    cudaGetSymbolAddress((void**)&kb, g_kb);
    cudaGetSymbolAddress((void**)&vb, g_vb);
    cudaGetSymbolAddress((void**)&qb, g_qb);
    cudaGetSymbolAddress((void**)&agga, g_agga);
    cudaGetSymbolAddress((void**)&aggb, g_aggb);
    cudaGetSymbolAddress((void**)&bfold, g_bfold);
    cudaGetSymbolAddress((void**)&wt, g_wt);
    cudaGetSymbolAddress((void**)&rp_ab, g_rp_ab);
    cudaGetSymbolAddress((void**)&rp_ba, g_rp_ba);
    cudaGetSymbolAddress((void**)&cnt, g_cnt);
    cudaGetSymbolAddress((void**)&cur, g_cur);
    cudaGetSymbolAddress((void**)&src_ab, g_src_ab);
    cudaGetSymbolAddress((void**)&src_ba, g_src_ba);

    cudaFuncSetAttribute(mm_gemm, cudaFuncAttributeMaxDynamicSharedMemorySize, SMEM_BYTES);

    // 1. fold rel matrices; convert weights to mma-ready layout
    fold_kernel<<<(131072 + 1024 + 255) / 256, 256>>>(k_w, k_b, v_w, v_b, a_rel, m_rel);
    convert_weights<<<(18 * 16384 + 255) / 256, 256>>>(lin_a_w, lin_b_w, q_w, a_lin_w);

    // 2. input linears (+relu)
    launch_mm_gemm(x_a, NA, DA, wt, 0, -1, -1, lin_a_b, nullptr, nullptr,
                   xa, nullptr, nullptr, 1, 1, nullptr, nullptr, 0);
    launch_mm_gemm(x_b, NB, DB, wt, 1, -1, -1, lin_b_b, nullptr, nullptr,
                   xb, nullptr, nullptr, 1, 1, nullptr, nullptr, 0);

    // 3. build CSRs (by destination)
    {
        zero_int<<<(NB + 255) / 256, 256>>>(cnt, NB);
        hist_kernel<<<(Eab + 255) / 256, 256>>>(edge_ab + Eab, Eab, cnt);
        scan_exclusive<<<1, 1024>>>(cnt, rp_ab, NB);
        copy_int<<<(NB + 255) / 256, 256>>>(rp_ab, cur, NB);
        scatter_kernel<<<(Eab + 255) / 256, 256>>>(edge_ab, edge_ab + Eab, Eab, cur, src_ab);

        zero_int<<<(NA + 255) / 256, 256>>>(cnt, NA);
        hist_kernel<<<(Eba + 255) / 256, 256>>>(edge_ba + Eba, Eba, cnt);
        scan_exclusive<<<1, 1024>>>(cnt, rp_ba, NA);
        copy_int<<<(NA + 255) / 256, 256>>>(rp_ba, cur, NA);
        scatter_kernel<<<(Eba + 255) / 256, 256>>>(edge_ba, edge_ba + Eba, Eba, cur, src_ba);
    }

    for (int l = 0; l < LNUM; l++) {
        int lt0 = l * 2 + 0, lt1 = l * 2 + 1;
        const float* bKA = bfold + (lt0 * 2 + 0) * CDIM;
        const float* bVA = bfold + (lt0 * 2 + 1) * CDIM;
        const float* bKB = bfold + (lt1 * 2 + 0) * CDIM;
        const float* bVB = bfold + (lt1 * 2 + 1) * CDIM;

        // fused K,V,Q for each node type
        launch_mm_gemm(xa, NA, CDIM, wt, 2 + lt0 * 4 + 0, 2 + lt0 * 4 + 1, 2 + lt0 * 4 + 2,
                       bKA, bVA, q_b + lt0 * CDIM, ka, va, qa, 3, 0, nullptr, nullptr, 0);
        launch_mm_gemm(xb, NB, CDIM, wt, 2 + lt1 * 4 + 0, 2 + lt1 * 4 + 1, 2 + lt1 * 4 + 2,
                       bKB, bVB, q_b + lt1 * CDIM, kb, vb, qb, 3, 0, nullptr, nullptr, 0);

        // aggregation (A->B relation 0, B->A relation 1)
        agg_kernel<<<(NB * 32 + 255) / 256, 256>>>(ka, va, qb, rp_ab, src_ab,
                                                   p_rel + lt0 * HNUM, aggb, NB);
        agg_kernel<<<(NA * 32 + 255) / 256, 256>>>(kb, vb, qa, rp_ba, src_ba,
                                                   p_rel + lt1 * HNUM, agga, NA);

        // gelu + a_lin + skip-mix; last layer writes directly to output
        float* dstA = (l == LNUM - 1) ? out : xa;
        float* dstB = (l == LNUM - 1) ? (out + (size_t)NA * CDIM) : xb;
        launch_mm_gemm(agga, NA, CDIM, wt, 2 + lt0 * 4 + 3, -1, -1,
                       a_lin_b + lt0 * CDIM, nullptr, nullptr,
                       dstA, nullptr, nullptr, 1, 2, xa, skip, lt0);
        launch_mm_gemm(aggb, NB, CDIM, wt, 2 + lt1 * 4 + 3, -1, -1,
                       a_lin_b + lt1 * CDIM, nullptr, nullptr,
                       dstB, nullptr, nullptr, 1, 2, xb, skip, lt1);
    }
}

// round 5
// speedup vs baseline: 2.3151x; 1.5988x over previous
#include <cuda_runtime.h>
#include <cuda_bf16.h>
#include <math.h>
#include <stdint.h>

#define CDIM 128
#define HNUM 4
#define DDIM 32
#define LNUM 2
#define MAXN 40000
#define MAXE 250000
#define INV_SQRT_D 0.17677669529663687f

// ---------------- static scratch (no allocs allowed) ----------------
__device__ float g_xa[MAXN * CDIM];
__device__ float g_xb[MAXN * CDIM];
__device__ float g_ka[MAXN * CDIM];
__device__ float g_va[MAXN * CDIM];
__device__ float g_qa[MAXN * CDIM];
__device__ float g_kb[MAXN * CDIM];
__device__ float g_vb[MAXN * CDIM];
__device__ float g_qb[MAXN * CDIM];
__device__ float g_agga[MAXN * CDIM];
__device__ float g_aggb[MAXN * CDIM];
__device__ float g_wfold[2][2][2][CDIM * CDIM]; // [l][t][k-or-v]
__device__ float g_bfold[2][2][2][CDIM];
// weight slots: [slot] 64KB = hi tile 32KB + lo tile 32KB; [n=128][k-pitch=128] bf16, XOR-swizzled
__device__ __align__(16) unsigned char g_wt[18 * 65536];
__device__ int g_cnt0[MAXN], g_cnt1[MAXN];
__device__ int g_st0[MAXN], g_st1[MAXN];
__device__ int g_cur0[MAXN], g_cur1[MAXN];
__device__ int g_tot[2];
__device__ int g_src_ab[MAXE];
__device__ int g_src_ba[MAXE];

// swizzled byte offset for element (row, k) in a [row][k] bf16 tile, pitch 128 elems
__device__ __forceinline__ uint32_t tile_off(int row, int k) {
    return (uint32_t)(row * 256 + (((k >> 3) ^ (row & 7)) << 4) + ((k & 7) << 1));
}
__device__ __forceinline__ uint32_t smem_u32(const void* p) {
    uint32_t a;
    asm("{ .reg .u64 t; cvta.to.shared.u64 t, %1; cvt.u32.u64 %0, t; }" : "=r"(a) : "l"(p));
    return a;
}
__device__ __forceinline__ void ldsm4(uint32_t& r0, uint32_t& r1, uint32_t& r2, uint32_t& r3, uint32_t addr) {
    asm volatile("ldmatrix.sync.aligned.m8n8.x4.shared.b16 {%0,%1,%2,%3}, [%4];"
                 : "=r"(r0), "=r"(r1), "=r"(r2), "=r"(r3) : "r"(addr));
}
__device__ __forceinline__ void mma16816(float* c, const uint32_t* a, const uint32_t* b) {
    asm volatile(
        "mma.sync.aligned.m16n8k16.row.col.f32.bf16.bf16.f32 "
        "{%0,%1,%2,%3}, {%4,%5,%6,%7}, {%8,%9}, {%0,%1,%2,%3};"
        : "+f"(c[0]), "+f"(c[1]), "+f"(c[2]), "+f"(c[3])
        : "r"(a[0]), "r"(a[1]), "r"(a[2]), "r"(a[3]), "r"(b[0]), "r"(b[1]));
}
__device__ __forceinline__ void cp16(uint32_t s, const void* g) {
    asm volatile("cp.async.cg.shared.global [%0], [%1], 16;" :: "r"(s), "l"(g) : "memory");
}
__device__ __forceinline__ void cp_commit() { asm volatile("cp.async.commit_group;" ::: "memory"); }
__device__ __forceinline__ void cp_wait0() { asm volatile("cp.async.wait_group 0;" ::: "memory"); }
__device__ __forceinline__ void cp_wait1() { asm volatile("cp.async.wait_group 1;" ::: "memory"); }

// ---------------- fold a_rel/m_rel (block-diag per head) into k_w/v_w ----------------
__global__ void fold_kernel(const float* __restrict__ kw, const float* __restrict__ kb,
                            const float* __restrict__ vw, const float* __restrict__ vb,
                            const float* __restrict__ arel, const float* __restrict__ mrel) {
    int tid = blockIdx.x * blockDim.x + threadIdx.x;
    if (tid < 131072) {
        int col = tid & 127;
        int i = (tid >> 7) & 127;
        int kv = (tid >> 14) & 1;
        int t = (tid >> 15) & 1;
        int l = (tid >> 16) & 1;
        int h = col >> 5;
        int e = col & 31;
        const float* W = kv ? vw : kw;
        const float* R = kv ? mrel : arel;
        const float* wblk = W + (l * 2 + t) * CDIM * CDIM;
        const float* rblk = R + ((l * 2 + t) * HNUM + h) * DDIM * DDIM;
        float s = 0.f;
#pragma unroll
        for (int d = 0; d < 32; d++)
            s += wblk[i * CDIM + h * 32 + d] * rblk[d * 32 + e];
        g_wfold[l][t][kv][i * CDIM + col] = s;
    } else if (tid < 131072 + 1024) {
        int idx = tid - 131072;
        int col = idx & 127;
        int kv = (idx >> 7) & 1;
        int t = (idx >> 8) & 1;
        int l = (idx >> 9) & 1;
        int h = col >> 5;
        int e = col & 31;
        const float* B = kv ? vb : kb;
        const float* R = kv ? mrel : arel;
        const float* bblk = B + (l * 2 + t) * CDIM;
        const float* rblk = R + ((l * 2 + t) * HNUM + h) * DDIM * DDIM;
        float s = 0.f;
#pragma unroll
        for (int d = 0; d < 32; d++)
            s += bblk[h * 32 + d] * rblk[d * 32 + e];
        g_bfold[l][t][kv][col] = s;
    }
}

// ---------------- convert weights: transpose to [n][k], split hi/lo, swizzle ----------------
// slot 0: lin_a_w (K=64); slot 1: lin_b_w (K=32); slot 2+(lt*4+j): j=0 Kfold, 1 Vfold, 2 q_w, 3 a_lin_w
__global__ void convert_weights(const float* __restrict__ lin_a_w, const float* __restrict__ lin_b_w,
                                const float* __restrict__ q_w, const float* __restrict__ a_lin_w) {
    int tid = blockIdx.x * blockDim.x + threadIdx.x;
    if (tid >= 18 * 16384) return;
    int s = tid >> 14;
    int rem = tid & 16383;
    int n = rem >> 7;
    int k = rem & 127;
    float val = 0.f;
    const float* wfold = &g_wfold[0][0][0][0];
    if (s == 0) {
        if (k < 64) val = lin_a_w[k * CDIM + n];
    } else if (s == 1) {
        if (k < 32) val = lin_b_w[k * CDIM + n];
    } else {
        int q = s - 2;
        int j = q & 3;
        int lt = q >> 2;
        if (j == 0) val = wfold[(lt * 2 + 0) * 16384 + k * CDIM + n];
        else if (j == 1) val = wfold[(lt * 2 + 1) * 16384 + k * CDIM + n];
        else if (j == 2) val = q_w[lt * 16384 + k * CDIM + n];
        else val = a_lin_w[lt * 16384 + k * CDIM + n];
    }
    __nv_bfloat16 hi = __float2bfloat16(val);
    __nv_bfloat16 lo = __float2bfloat16(val - __bfloat162float(hi));
    uint32_t off = tile_off(n, k);
    *(__nv_bfloat16*)(g_wt + (size_t)s * 65536 + off) = hi;
    *(__nv_bfloat16*)(g_wt + (size_t)s * 65536 + 32768 + off) = lo;
}

// ---------------- merged two-type tensor-core GEMM ----------------
struct GSide {
    const float* A;
    const unsigned char* W[3]; // 64KB slot (hi + lo)
    const float* bias[3];
    float* out[3];
    const float* xold;
    int M, K, skipIdx;
};
struct GArgs {
    GSide s[2];
    const float* skipPtr;
    int nOut, mode, tiles0;
};

#define SM_AHI 0
#define SM_ALO 32768
#define SM_W 65536
#define SMEM_BYTES 196608

__global__ void __launch_bounds__(256, 1) mm2(GArgs g) {
    extern __shared__ __align__(16) unsigned char smem[];
    uint32_t sb = smem_u32(smem);
    int tid = threadIdx.x;
    int wid = tid >> 5, lane = tid & 31;
    int warp_m = wid & 3, warp_n = wid >> 2;
    int side = (blockIdx.x >= (unsigned)g.tiles0) ? 1 : 0;
    GSide S = g.s[side];
    int tile = side ? (blockIdx.x - g.tiles0) : blockIdx.x;
    int m0 = tile * 128;

    // stage W[0] via cp.async (overlaps with A convert below)
    {
        const unsigned char* w = S.W[0];
        for (int i = tid * 16; i < 65536; i += 256 * 16) cp16(sb + SM_W + i, w + i);
        cp_commit();
    }

    // zero A region if K-padded or partial M tile
    if (S.K != 128 || m0 + 128 > S.M) {
        uint4 z = make_uint4(0, 0, 0, 0);
        for (int i = tid; i < 65536 / 16; i += 256) ((uint4*)(smem + SM_AHI))[i] = z;
        __syncthreads();
    }

    // load + convert A (optional gelu) into split bf16 swizzled tiles
    {
        int kvec = S.K >> 2;
        int tot = 128 * kvec;
        for (int i = tid; i < tot; i += 256) {
            int row = i / kvec, c4 = i - row * kvec;
            int grow = m0 + row;
            if (grow < S.M) {
                float4 v = *(const float4*)(S.A + (size_t)grow * S.K + c4 * 4);
                if (g.mode == 2) {
                    v.x = 0.5f * v.x * (1.f + erff(v.x * 0.70710678118654752f));
                    v.y = 0.5f * v.y * (1.f + erff(v.y * 0.70710678118654752f));
                    v.z = 0.5f * v.z * (1.f + erff(v.z * 0.70710678118654752f));
                    v.w = 0.5f * v.w * (1.f + erff(v.w * 0.70710678118654752f));
                }
                __nv_bfloat16 hx = __float2bfloat16(v.x), hy = __float2bfloat16(v.y);
                __nv_bfloat16 hz = __float2bfloat16(v.z), hw = __float2bfloat16(v.w);
                __nv_bfloat162 h01, h23, l01, l23;
                h01.x = hx; h01.y = hy; h23.x = hz; h23.y = hw;
                l01.x = __float2bfloat16(v.x - __bfloat162float(hx));
                l01.y = __float2bfloat16(v.y - __bfloat162float(hy));
                l23.x = __float2bfloat16(v.z - __bfloat162float(hz));
                l23.y = __float2bfloat16(v.w - __bfloat162float(hw));
                uint32_t off = tile_off(row, c4 * 4);
                uint2 hv, lv;
                hv.x = *(uint32_t*)&h01; hv.y = *(uint32_t*)&h23;
                lv.x = *(uint32_t*)&l01; lv.y = *(uint32_t*)&l23;
                *(uint2*)(smem + SM_AHI + off) = hv;
                *(uint2*)(smem + SM_ALO + off) = lv;
            }
        }
    }

    for (int o = 0; o < g.nOut; o++) {
        // prefetch next W into the other buffer, then wait for current
        if (o + 1 < g.nOut) {
            const unsigned char* w = S.W[o + 1];
            uint32_t db = SM_W + ((o + 1) & 1) * 65536;
            for (int i = tid * 16; i < 65536; i += 256 * 16) cp16(sb + db + i, w + i);
            cp_commit();
            cp_wait1();
        } else {
            cp_wait0();
        }
        __syncthreads();
        uint32_t wb = SM_W + (o & 1) * 65536;

        float acc[2][8][4];
#pragma unroll
        for (int mt = 0; mt < 2; mt++)
#pragma unroll
            for (int nt = 0; nt < 8; nt++)
#pragma unroll
                for (int e = 0; e < 4; e++) acc[mt][nt][e] = 0.f;

        for (int kc = 0; kc < S.K; kc += 16) {
            int kch = kc >> 3;
            uint32_t ah[8], al[8], bh[16], bl[16];
#pragma unroll
            for (int mt = 0; mt < 2; mt++) {
                int r = warp_m * 32 + mt * 16 + (lane & 15);
                uint32_t addr = sb + SM_AHI + r * 256 + ((((kch + (lane >> 4)) ^ (r & 7))) << 4);
                ldsm4(ah[mt * 4 + 0], ah[mt * 4 + 1], ah[mt * 4 + 2], ah[mt * 4 + 3], addr);
                ldsm4(al[mt * 4 + 0], al[mt * 4 + 1], al[mt * 4 + 2], al[mt * 4 + 3], addr + 32768);
            }
#pragma unroll
            for (int p = 0; p < 4; p++) {
                int n = warp_n * 64 + p * 16 + ((lane >> 4) << 3) + (lane & 7);
                uint32_t addr = sb + wb + n * 256 + ((((kch + ((lane >> 3) & 1)) ^ (n & 7))) << 4);
                ldsm4(bh[p * 4 + 0], bh[p * 4 + 1], bh[p * 4 + 2], bh[p * 4 + 3], addr);
                ldsm4(bl[p * 4 + 0], bl[p * 4 + 1], bl[p * 4 + 2], bl[p * 4 + 3], addr + 32768);
            }
#pragma unroll
            for (int mt = 0; mt < 2; mt++)
#pragma unroll
                for (int nt = 0; nt < 8; nt++) {
                    float* c = acc[mt][nt];
                    mma16816(c, &ah[mt * 4], &bh[nt * 2]);
                    mma16816(c, &ah[mt * 4], &bl[nt * 2]);
                    mma16816(c, &al[mt * 4], &bh[nt * 2]);
                }
        }

        // epilogue straight from registers
        float sg = 1.f, om = 0.f;
        if (g.mode == 2) {
            float sk = g.skipPtr[S.skipIdx];
            sg = 1.f / (1.f + expf(-sk));
            om = 1.f - sg;
        }
        const float* bp = S.bias[o];
        float* op = S.out[o];
        int qrow = lane >> 2, qcol = (lane & 3) * 2;
        float2 bv[8];
#pragma unroll
        for (int nt = 0; nt < 8; nt++)
            bv[nt] = *(const float2*)&bp[warp_n * 64 + nt * 8 + qcol];
#pragma unroll
        for (int mt = 0; mt < 2; mt++) {
#pragma unroll
            for (int half = 0; half < 2; half++) {
                int row = m0 + warp_m * 32 + mt * 16 + qrow + half * 8;
                if (row >= S.M) continue;
#pragma unroll
                for (int nt = 0; nt < 8; nt++) {
                    int col = warp_n * 64 + nt * 8 + qcol;
                    float vx = acc[mt][nt][half * 2 + 0] + bv[nt].x;
                    float vy = acc[mt][nt][half * 2 + 1] + bv[nt].y;
                    if (g.mode == 1) {
                        vx = fmaxf(vx, 0.f);
                        vy = fmaxf(vy, 0.f);
                    } else if (g.mode == 2) {
                        float2 xo = *(const float2*)&S.xold[(size_t)row * CDIM + col];
                        vx = sg * vx + om * xo.x;
                        vy = sg * vy + om * xo.y;
                    }
                    float2 ov; ov.x = vx; ov.y = vy;
                    *(float2*)&op[(size_t)row * CDIM + col] = ov;
                }
            }
        }
        __syncthreads(); // all reads of wb done before next prefetch overwrites buffers
    }
}

// ---------------- CSR build (scan-free: atomic range allocation) ----------------
__global__ void csr_zero(int nA, int nB) {
    int i = blockIdx.x * blockDim.x + threadIdx.x;
    if (i < nB) g_cnt0[i] = 0;
    if (i < nA) g_cnt1[i] = 0;
    if (i == 0) { g_tot[0] = 0; g_tot[1] = 0; }
}
__global__ void hist_both(const int* __restrict__ dab, int Eab,
                          const int* __restrict__ dba, int Eba) {
    int i = blockIdx.x * blockDim.x + threadIdx.x;
    if (i < Eab) atomicAdd(&g_cnt0[dab[i]], 1);
    else if (i < Eab + Eba) atomicAdd(&g_cnt1[dba[i - Eab]], 1);
}
__global__ void alloc_ranges(int nA, int nB) {
    int i = blockIdx.x * blockDim.x + threadIdx.x;
    if (i < nB) {
        int c = g_cnt0[i];
        int p = atomicAdd(&g_tot[0], c);
        g_st0[i] = p; g_cur0[i] = p;
    }
    if (i < nA) {
        int c = g_cnt1[i];
        int p = atomicAdd(&g_tot[1], c);
        g_st1[i] = p; g_cur1[i] = p;
    }
}
__global__ void scatter_both(const int* __restrict__ sab, const int* __restrict__ dab, int Eab,
                             const int* __restrict__ sba, const int* __restrict__ dba, int Eba) {
    int i = blockIdx.x * blockDim.x + threadIdx.x;
    if (i < Eab) {
        int p = atomicAdd(&g_cur0[dab[i]], 1);
        g_src_ab[p] = sab[i];
    } else if (i < Eab + Eba) {
        int j = i - Eab;
        int p = atomicAdd(&g_cur1[dba[j]], 1);
        g_src_ba[p] = sba[j];
    }
}

// ---------------- merged per-destination online-softmax aggregation ----------------
struct ASide {
    const float* Kf;
    const float* Vf;
    const float* Qf;
    const float* prel;
    const int* start;
    const int* cnt;
    const int* src;
    float* Out;
    int N;
};
struct AArgs {
    ASide s[2];
    int blocks0;
};

__global__ void __launch_bounds__(256) agg2(AArgs g) {
    int side = (blockIdx.x >= (unsigned)g.blocks0) ? 1 : 0;
    ASide S = g.s[side];
    int blk = side ? (blockIdx.x - g.blocks0) : blockIdx.x;
    int w = blk * 8 + (threadIdx.x >> 5);
    int lane = threadIdx.x & 31;
    if (w >= S.N) return;
    const float4 q = *(const float4*)&S.Qf[(size_t)w * CDIM + lane * 4];
    float pr = S.prel[lane >> 3] * INV_SQRT_D;
    int e0 = S.start[w];
    int e1 = e0 + S.cnt[w];
    float m = -INFINITY, sum = 0.f;
    float ax = 0.f, ay = 0.f, az = 0.f, aw2 = 0.f;
    float4 kc, vc;
    if (e0 < e1) {
        int s0 = S.src[e0];
        kc = *(const float4*)&S.Kf[(size_t)s0 * CDIM + lane * 4];
        vc = *(const float4*)&S.Vf[(size_t)s0 * CDIM + lane * 4];
    }
    for (int j = e0; j < e1; j++) {
        float4 kn = kc, vn = vc;
        if (j + 1 < e1) {
            int s1 = S.src[j + 1];
            kn = *(const float4*)&S.Kf[(size_t)s1 * CDIM + lane * 4];
            vn = *(const float4*)&S.Vf[(size_t)s1 * CDIM + lane * 4];
        }
        float d = q.x * kc.x + q.y * kc.y + q.z * kc.z + q.w * kc.w;
        d += __shfl_xor_sync(0xffffffffu, d, 1);
        d += __shfl_xor_sync(0xffffffffu, d, 2);
        d += __shfl_xor_sync(0xffffffffu, d, 4);
        float logit = d * pr;
        float mn = fmaxf(m, logit);
        float sc = __expf(m - mn);   // m=-inf first iter -> 0
        float wg = __expf(logit - mn);
        sum = sum * sc + wg;
        ax = ax * sc + wg * vc.x;
        ay = ay * sc + wg * vc.y;
        az = az * sc + wg * vc.z;
        aw2 = aw2 * sc + wg * vc.w;
        m = mn;
        kc = kn; vc = vn;
    }
    float inv = 1.f / (sum + 1e-16f);
    float4 o = make_float4(ax * inv, ay * inv, az * inv, aw2 * inv);
    *(float4*)&S.Out[(size_t)w * CDIM + lane * 4] = o;
}

// ---------------- driver ----------------
extern "C" void kernel_launch(void* const* d_in, const int* in_sizes, int n_in,
                              void* d_out, int out_size) {
    const float* x_a = (const float*)d_in[0];
    const float* x_b = (const float*)d_in[1];
    const int* edge_ab = (const int*)d_in[2];
    const int* edge_ba = (const int*)d_in[3];
    const float* lin_a_b = (const float*)d_in[5];
    const float* lin_b_b = (const float*)d_in[7];
    const float* k_w = (const float*)d_in[8];
    const float* k_b = (const float*)d_in[9];
    const float* q_w = (const float*)d_in[10];
    const float* q_b = (const float*)d_in[11];
    const float* v_w = (const float*)d_in[12];
    const float* v_b = (const float*)d_in[13];
    const float* a_rel = (const float*)d_in[14];
    const float* m_rel = (const float*)d_in[15];
    const float* p_rel = (const float*)d_in[16];
    const float* a_lin_w = (const float*)d_in[17];
    const float* a_lin_b = (const float*)d_in[18];
    const float* skip = (const float*)d_in[19];
    float* out = (float*)d_out;

    int DA = in_sizes[4] / CDIM;
    int DB = in_sizes[6] / CDIM;
    int NA = in_sizes[0] / DA;
    int NB = in_sizes[1] / DB;
    int Eab = in_sizes[2] / 2;
    int Eba = in_sizes[3] / 2;

    float *xa, *xb, *ka, *va, *qa, *kb, *vb, *qb, *agga, *aggb, *bfold;
    unsigned char* wt;
    int *st0, *st1, *cnt0, *cnt1, *src_ab, *src_ba;
    cudaGetSymbolAddress((void**)&xa, g_xa);
    cudaGetSymbolAddress((void**)&xb, g_xb);
    cudaGetSymbolAddress((void**)&ka, g_ka);
    cudaGetSymbolAddress((void**)&va, g_va);
    cudaGetSymbolAddress((void**)&qa, g_qa);
    cudaGetSymbolAddress((void**)&kb, g_kb);
    cudaGetSymbolAddress((void**)&vb, g_vb);
    cudaGetSymbolAddress((void**)&qb, g_qb);
    cudaGetSymbolAddress((void**)&agga, g_agga);
    cudaGetSymbolAddress((void**)&aggb, g_aggb);
    cudaGetSymbolAddress((void**)&bfold, g_bfold);
    cudaGetSymbolAddress((void**)&wt, g_wt);
    cudaGetSymbolAddress((void**)&st0, g_st0);
    cudaGetSymbolAddress((void**)&st1, g_st1);
    cudaGetSymbolAddress((void**)&cnt0, g_cnt0);
    cudaGetSymbolAddress((void**)&cnt1, g_cnt1);
    cudaGetSymbolAddress((void**)&src_ab, g_src_ab);
    cudaGetSymbolAddress((void**)&src_ba, g_src_ba);

    cudaFuncSetAttribute(mm2, cudaFuncAttributeMaxDynamicSharedMemorySize, SMEM_BYTES);

    int tilesA = (NA + 127) / 128, tilesB = (NB + 127) / 128;

    // 1. fold rel matrices; convert weights to mma-ready layout
    fold_kernel<<<(131072 + 1024 + 255) / 256, 256>>>(k_w, k_b, v_w, v_b, a_rel, m_rel);
    convert_weights<<<(18 * 16384 + 255) / 256, 256>>>((const float*)d_in[4], (const float*)d_in[6], q_w, a_lin_w);

    // 2. input linears (+relu), both node types in one launch
    {
        GArgs g = {};
        g.s[0].A = x_a; g.s[0].W[0] = wt + (size_t)0 * 65536;
        g.s[0].bias[0] = lin_a_b; g.s[0].out[0] = xa;
        g.s[0].M = NA; g.s[0].K = DA;
        g.s[1].A = x_b; g.s[1].W[0] = wt + (size_t)1 * 65536;
        g.s[1].bias[0] = lin_b_b; g.s[1].out[0] = xb;
        g.s[1].M = NB; g.s[1].K = DB;
        g.nOut = 1; g.mode = 1; g.tiles0 = tilesA;
        mm2<<<tilesA + tilesB, 256, SMEM_BYTES>>>(g);
    }

    // 3. build CSRs (scan-free)
    {
        int nmax = (NA > NB ? NA : NB);
        int etot = Eab + Eba;
        csr_zero<<<(nmax + 255) / 256, 256>>>(NA, NB);
        hist_both<<<(etot + 255) / 256, 256>>>(edge_ab + Eab, Eab, edge_ba + Eba, Eba);
        alloc_ranges<<<(nmax + 255) / 256, 256>>>(NA, NB);
        scatter_both<<<(etot + 255) / 256, 256>>>(edge_ab, edge_ab + Eab, Eab,
                                                  edge_ba, edge_ba + Eba, Eba);
    }

    for (int l = 0; l < LNUM; l++) {
        int lt0 = l * 2 + 0, lt1 = l * 2 + 1;

        // fused K,V,Q for both node types in one launch
        {
            GArgs g = {};
            g.s[0].A = xa;
            g.s[0].W[0] = wt + (size_t)(2 + lt0 * 4 + 0) * 65536;
            g.s[0].W[1] = wt + (size_t)(2 + lt0 * 4 + 1) * 65536;
            g.s[0].W[2] = wt + (size_t)(2 + lt0 * 4 + 2) * 65536;
            g.s[0].bias[0] = bfold + (lt0 * 2 + 0) * CDIM;
            g.s[0].bias[1] = bfold + (lt0 * 2 + 1) * CDIM;
            g.s[0].bias[2] = q_b + lt0 * CDIM;
            g.s[0].out[0] = ka; g.s[0].out[1] = va; g.s[0].out[2] = qa;
            g.s[0].M = NA; g.s[0].K = CDIM;
            g.s[1].A = xb;
            g.s[1].W[0] = wt + (size_t)(2 + lt1 * 4 + 0) * 65536;
            g.s[1].W[1] = wt + (size_t)(2 + lt1 * 4 + 1) * 65536;
            g.s[1].W[2] = wt + (size_t)(2 + lt1 * 4 + 2) * 65536;
            g.s[1].bias[0] = bfold + (lt1 * 2 + 0) * CDIM;
            g.s[1].bias[1] = bfold + (lt1 * 2 + 1) * CDIM;
            g.s[1].bias[2] = q_b + lt1 * CDIM;
            g.s[1].out[0] = kb; g.s[1].out[1] = vb; g.s[1].out[2] = qb;
            g.s[1].M = NB; g.s[1].K = CDIM;
            g.nOut = 3; g.mode = 0; g.tiles0 = tilesA;
            mm2<<<tilesA + tilesB, 256, SMEM_BYTES>>>(g);
        }

        // both aggregations in one launch (A->B rel 0 into aggb; B->A rel 1 into agga)
        {
            AArgs a = {};
            a.s[0].Kf = ka; a.s[0].Vf = va; a.s[0].Qf = qb;
            a.s[0].prel = p_rel + lt0 * HNUM;
            a.s[0].start = st0; a.s[0].cnt = cnt0; a.s[0].src = src_ab;
            a.s[0].Out = aggb; a.s[0].N = NB;
            a.s[1].Kf = kb; a.s[1].Vf = vb; a.s[1].Qf = qa;
            a.s[1].prel = p_rel + lt1 * HNUM;
            a.s[1].start = st1; a.s[1].cnt = cnt1; a.s[1].src = src_ba;
            a.s[1].Out = agga; a.s[1].N = NA;
            int b0 = (NB + 7) / 8, b1 = (NA + 7) / 8;
            a.blocks0 = b0;
            agg2<<<b0 + b1, 256>>>(a);
        }

        // gelu + a_lin + skip-mix for both types; last layer writes directly to output
        {
            float* dstA = (l == LNUM - 1) ? out : xa;
            float* dstB = (l == LNUM - 1) ? (out + (size_t)NA * CDIM) : xb;
            GArgs g = {};
            g.s[0].A = agga;
            g.s[0].W[0] = wt + (size_t)(2 + lt0 * 4 + 3) * 65536;
            g.s[0].bias[0] = a_lin_b + lt0 * CDIM;
            g.s[0].out[0] = dstA;
            g.s[0].xold = xa; g.s[0].M = NA; g.s[0].K = CDIM; g.s[0].skipIdx = lt0;
            g.s[1].A = aggb;
            g.s[1].W[0] = wt + (size_t)(2 + lt1 * 4 + 3) * 65536;
            g.s[1].bias[0] = a_lin_b + lt1 * CDIM;
            g.s[1].out[0] = dstB;
            g.s[1].xold = xb; g.s[1].M = NB; g.s[1].K = CDIM; g.s[1].skipIdx = lt1;
            g.skipPtr = skip;
            g.nOut = 1; g.mode = 2; g.tiles0 = tilesA;
            mm2<<<tilesA + tilesB, 256, SMEM_BYTES>>>(g);
        }
    }
}